// round 3
// baseline (speedup 1.0000x reference)
#include <cuda_runtime.h>

#define N_NODES 50000
#define N_EDGES 10000
#define NNZ     800000
#define C       256
#define NEG     0.01f

// ---------------- scratch (device globals; no allocation allowed) ----------------
__device__ float d_e0[N_EDGES * C];     // edge aggregation (pre-Binv)
__device__ float d_z[N_NODES * C];      // node aggregation (pre-Dinv)
__device__ float d_y[N_NODES * C];      // leaky(conv output)
__device__ float d_Dcnt[N_NODES];       // node degrees
__device__ float d_Bcnt[N_EDGES];       // hyperedge degrees
__device__ float d_gram[C * C];         // y^T y

__device__ __forceinline__ float leaky(float v) {
    return v > 0.f ? v : NEG * v;
}

__device__ __forceinline__ void red_add4(float* p, float4 v) {
    asm volatile("red.global.add.v4.f32 [%0], {%1,%2,%3,%4};"
                 :: "l"(p), "f"(v.x), "f"(v.y), "f"(v.z), "f"(v.w) : "memory");
}

// ---------------- zero init ----------------
__global__ void zero_kernel() {
    size_t i = (size_t)blockIdx.x * blockDim.x + threadIdx.x;
    size_t stride = (size_t)gridDim.x * blockDim.x;
    float4 z4 = make_float4(0.f, 0.f, 0.f, 0.f);
    float4* z = (float4*)d_z;
    for (size_t j = i; j < (size_t)N_NODES * C / 4; j += stride) z[j] = z4;
    float4* e = (float4*)d_e0;
    for (size_t j = i; j < (size_t)N_EDGES * C / 4; j += stride) e[j] = z4;
    for (size_t j = i; j < N_NODES; j += stride) d_Dcnt[j] = 0.f;
    for (size_t j = i; j < N_EDGES; j += stride) d_Bcnt[j] = 0.f;
    for (size_t j = i; j < C * C; j += stride) d_gram[j] = 0.f;
}

// ---------------- degrees ----------------
__global__ void degree_kernel(const int* __restrict__ nidx, const int* __restrict__ eidx) {
    int i = blockIdx.x * blockDim.x + threadIdx.x;
    if (i < NNZ) {
        atomicAdd(&d_Dcnt[nidx[i]], 1.f);
        atomicAdd(&d_Bcnt[eidx[i]], 1.f);
    }
}

// ---------------- scatter 1: e0 += emb[node]  (per incidence) ----------------
// 64 threads per incidence, one float4 per thread -> coalesced 1KB row moves.
__global__ void scatter1_kernel(const float* __restrict__ emb,
                                const int* __restrict__ nidx,
                                const int* __restrict__ eidx) {
    long long t = (long long)blockIdx.x * blockDim.x + threadIdx.x;
    int inc = (int)(t >> 6);
    if (inc >= NNZ) return;
    int c = ((int)t & 63) << 2;
    int nr = __ldg(nidx + inc);
    int er = __ldg(eidx + inc);
    float4 v = *(const float4*)(emb + (size_t)nr * C + c);
    red_add4(d_e0 + (size_t)er * C + c, v);
}

// ---------------- scatter 2: z += (e0[edge] * Binv)  (per incidence) ----------------
__global__ void scatter2_kernel(const int* __restrict__ nidx,
                                const int* __restrict__ eidx) {
    long long t = (long long)blockIdx.x * blockDim.x + threadIdx.x;
    int inc = (int)(t >> 6);
    if (inc >= NNZ) return;
    int c = ((int)t & 63) << 2;
    int nr = __ldg(nidx + inc);
    int er = __ldg(eidx + inc);
    float b = d_Bcnt[er];
    float binv = b > 0.f ? 1.f / b : 0.f;
    float4 v = *(const float4*)(d_e0 + (size_t)er * C + c);
    v.x *= binv; v.y *= binv; v.z *= binv; v.w *= binv;
    red_add4(d_z + (size_t)nr * C + c, v);
}

// ---------------- GEMM 1: y = leaky(Dinv * (z @ W^T) + conv_b) ----------------
// 128x128 tile, BK=16, 256 threads, 8x8 per thread.
#define BM 128
#define BN 128
#define BK 16

__global__ __launch_bounds__(256)
void gemm1_kernel(const float* __restrict__ W, const float* __restrict__ convb) {
    __shared__ __align__(16) float As[BK][BM + 4];
    __shared__ __align__(16) float Bs[BK][BN + 4];
    int rowBase = blockIdx.x * BM;
    int colBase = blockIdx.y * BN;
    int tid = threadIdx.x;
    int tx = tid & 15, ty = tid >> 4;
    float acc[8][8] = {};

    for (int k0 = 0; k0 < C; k0 += BK) {
        #pragma unroll
        for (int l = 0; l < 2; l++) {
            int idx = tid + l * 256;
            int r  = idx >> 2;          // 0..127
            int k4 = (idx & 3) << 2;    // 0,4,8,12
            float4 v = make_float4(0.f, 0.f, 0.f, 0.f);
            int gr = rowBase + r;
            if (gr < N_NODES) v = *(const float4*)(d_z + (size_t)gr * C + k0 + k4);
            As[k4 + 0][r] = v.x; As[k4 + 1][r] = v.y; As[k4 + 2][r] = v.z; As[k4 + 3][r] = v.w;
            float4 w = *(const float4*)(W + (size_t)(colBase + r) * C + k0 + k4);
            Bs[k4 + 0][r] = w.x; Bs[k4 + 1][r] = w.y; Bs[k4 + 2][r] = w.z; Bs[k4 + 3][r] = w.w;
        }
        __syncthreads();
        #pragma unroll
        for (int k = 0; k < BK; k++) {
            float4 a0 = *(const float4*)&As[k][ty * 8];
            float4 a1 = *(const float4*)&As[k][ty * 8 + 4];
            float4 b0 = *(const float4*)&Bs[k][tx * 8];
            float4 b1 = *(const float4*)&Bs[k][tx * 8 + 4];
            float a[8] = {a0.x, a0.y, a0.z, a0.w, a1.x, a1.y, a1.z, a1.w};
            float b[8] = {b0.x, b0.y, b0.z, b0.w, b1.x, b1.y, b1.z, b1.w};
            #pragma unroll
            for (int i = 0; i < 8; i++)
                #pragma unroll
                for (int j = 0; j < 8; j++)
                    acc[i][j] += a[i] * b[j];
        }
        __syncthreads();
    }

    #pragma unroll
    for (int i = 0; i < 8; i++) {
        int r = rowBase + ty * 8 + i;
        if (r < N_NODES) {
            float dc = d_Dcnt[r];
            float dinv = dc > 0.f ? 1.f / dc : 0.f;
            #pragma unroll
            for (int jg = 0; jg < 2; jg++) {
                int c0 = colBase + tx * 8 + jg * 4;
                float4 o;
                o.x = leaky(acc[i][jg * 4 + 0] * dinv + __ldg(&convb[c0 + 0]));
                o.y = leaky(acc[i][jg * 4 + 1] * dinv + __ldg(&convb[c0 + 1]));
                o.z = leaky(acc[i][jg * 4 + 2] * dinv + __ldg(&convb[c0 + 2]));
                o.w = leaky(acc[i][jg * 4 + 3] * dinv + __ldg(&convb[c0 + 3]));
                *(float4*)(d_y + (size_t)r * C + c0) = o;
            }
        }
    }
}

// ---------------- Gram: g = y^T y, split-K with atomics ----------------
#define KC 512

__global__ __launch_bounds__(256)
void gram_kernel() {
    __shared__ __align__(16) float Ai[BK][BM + 4];
    __shared__ __align__(16) float Aj[BK][BN + 4];
    int ci = blockIdx.x * 128;
    int cj = blockIdx.y * 128;
    int k0 = blockIdx.z * KC;
    int tid = threadIdx.x;
    int tx = tid & 15, ty = tid >> 4;
    float acc[8][8] = {};

    for (int kt = k0; kt < k0 + KC; kt += BK) {
        #pragma unroll
        for (int l = 0; l < 2; l++) {
            int idx = tid + l * 256;
            int kr = idx >> 5;          // 0..15
            int c4 = (idx & 31) << 2;   // 0..124
            int gk = kt + kr;
            float4 vi = make_float4(0.f, 0.f, 0.f, 0.f);
            float4 vj = make_float4(0.f, 0.f, 0.f, 0.f);
            if (gk < N_NODES) {
                vi = *(const float4*)(d_y + (size_t)gk * C + ci + c4);
                vj = *(const float4*)(d_y + (size_t)gk * C + cj + c4);
            }
            *(float4*)&Ai[kr][c4] = vi;
            *(float4*)&Aj[kr][c4] = vj;
        }
        __syncthreads();
        #pragma unroll
        for (int k = 0; k < BK; k++) {
            float4 a0 = *(const float4*)&Ai[k][ty * 8];
            float4 a1 = *(const float4*)&Ai[k][ty * 8 + 4];
            float4 b0 = *(const float4*)&Aj[k][tx * 8];
            float4 b1 = *(const float4*)&Aj[k][tx * 8 + 4];
            float a[8] = {a0.x, a0.y, a0.z, a0.w, a1.x, a1.y, a1.z, a1.w};
            float b[8] = {b0.x, b0.y, b0.z, b0.w, b1.x, b1.y, b1.z, b1.w};
            #pragma unroll
            for (int i = 0; i < 8; i++)
                #pragma unroll
                for (int j = 0; j < 8; j++)
                    acc[i][j] += a[i] * b[j];
        }
        __syncthreads();
    }

    #pragma unroll
    for (int i = 0; i < 8; i++)
        #pragma unroll
        for (int j = 0; j < 8; j++)
            atomicAdd(&d_gram[(size_t)(ci + ty * 8 + i) * C + cj + tx * 8 + j], acc[i][j]);
}

// ---------------- final: out = leaky(gram @ lin_w^T + lin_b), 256x256 ----------------
__global__ __launch_bounds__(256)
void final_kernel(const float* __restrict__ linw, const float* __restrict__ linb,
                  float* __restrict__ out) {
    __shared__ __align__(16) float As[16][68];
    __shared__ __align__(16) float Bs[16][68];
    int rowBase = blockIdx.y * 64;
    int colBase = blockIdx.x * 64;
    int tid = threadIdx.x;
    int tx = tid & 15, ty = tid >> 4;
    float acc[4][4] = {};

    for (int k0 = 0; k0 < C; k0 += 16) {
        int r  = tid >> 2;          // 0..63
        int k4 = (tid & 3) << 2;
        float4 v = *(const float4*)(d_gram + (size_t)(rowBase + r) * C + k0 + k4);
        As[k4 + 0][r] = v.x; As[k4 + 1][r] = v.y; As[k4 + 2][r] = v.z; As[k4 + 3][r] = v.w;
        float4 w = *(const float4*)(linw + (size_t)(colBase + r) * C + k0 + k4);
        Bs[k4 + 0][r] = w.x; Bs[k4 + 1][r] = w.y; Bs[k4 + 2][r] = w.z; Bs[k4 + 3][r] = w.w;
        __syncthreads();
        #pragma unroll
        for (int k = 0; k < 16; k++) {
            float4 a4 = *(const float4*)&As[k][ty * 4];
            float4 b4 = *(const float4*)&Bs[k][tx * 4];
            float a[4] = {a4.x, a4.y, a4.z, a4.w};
            float b[4] = {b4.x, b4.y, b4.z, b4.w};
            #pragma unroll
            for (int i = 0; i < 4; i++)
                #pragma unroll
                for (int j = 0; j < 4; j++)
                    acc[i][j] += a[i] * b[j];
        }
        __syncthreads();
    }

    #pragma unroll
    for (int i = 0; i < 4; i++) {
        int r = rowBase + ty * 4 + i;
        int c0 = colBase + tx * 4;
        float4 o;
        o.x = leaky(acc[i][0] + __ldg(&linb[c0 + 0]));
        o.y = leaky(acc[i][1] + __ldg(&linb[c0 + 1]));
        o.z = leaky(acc[i][2] + __ldg(&linb[c0 + 2]));
        o.w = leaky(acc[i][3] + __ldg(&linb[c0 + 3]));
        *(float4*)(out + (size_t)r * C + c0) = o;
    }
}

// ---------------- launch ----------------
extern "C" void kernel_launch(void* const* d_in, const int* in_sizes, int n_in,
                              void* d_out, int out_size) {
    const float* emb    = (const float*)d_in[0];
    const float* conv_w = (const float*)d_in[1];
    const float* conv_b = (const float*)d_in[2];
    const float* lin_w  = (const float*)d_in[3];
    const float* lin_b  = (const float*)d_in[4];
    const int*   eidx_all = (const int*)d_in[5];
    const int*   nidx = eidx_all;          // edge_index[0]
    const int*   eidx = eidx_all + NNZ;    // edge_index[1]
    float* out = (float*)d_out;

    zero_kernel<<<4096, 256>>>();
    degree_kernel<<<(NNZ + 255) / 256, 256>>>(nidx, eidx);
    scatter1_kernel<<<NNZ / 4, 256>>>(emb, nidx, eidx);
    scatter2_kernel<<<NNZ / 4, 256>>>(nidx, eidx);
    gemm1_kernel<<<dim3((N_NODES + BM - 1) / BM, C / BN), 256>>>(conv_w, conv_b);
    gram_kernel<<<dim3(C / 128, C / 128, (N_NODES + KC - 1) / KC), 256>>>();
    final_kernel<<<dim3(C / 64, C / 64), 256>>>(lin_w, lin_b, out);
}

// round 4
// speedup vs baseline: 1.3482x; 1.3482x over previous
#include <cuda_runtime.h>

#define N_NODES 50000
#define N_EDGES 10000
#define NNZ     800000
#define C       256
#define NEG     0.01f

// ---------------- scratch (device globals) ----------------
__device__ float d_e0[N_EDGES * C];     // edge aggregation of raw emb
__device__ float d_e1[N_EDGES * C];     // Binv * (e0 @ conv_w^T)
__device__ float d_zw[N_NODES * C];     // node aggregation of e1 (= z @ W^T)
__device__ float d_Dinv[N_NODES];       // 1/node degree
__device__ float d_Binv[N_EDGES];       // 1/edge degree
__device__ float d_gram[C * C];         // y^T y

__device__ __forceinline__ float leaky(float v) {
    return v > 0.f ? v : NEG * v;
}

__device__ __forceinline__ void red_add4(float* p, float4 v) {
    asm volatile("red.global.add.v4.f32 [%0], {%1,%2,%3,%4};"
                 :: "l"(p), "f"(v.x), "f"(v.y), "f"(v.z), "f"(v.w) : "memory");
}

// ---------------- zero init ----------------
__global__ void zero_kernel() {
    size_t i = (size_t)blockIdx.x * blockDim.x + threadIdx.x;
    size_t stride = (size_t)gridDim.x * blockDim.x;
    float4 z4 = make_float4(0.f, 0.f, 0.f, 0.f);
    float4* z = (float4*)d_zw;
    for (size_t j = i; j < (size_t)N_NODES * C / 4; j += stride) z[j] = z4;
    float4* e = (float4*)d_e0;
    for (size_t j = i; j < (size_t)N_EDGES * C / 4; j += stride) e[j] = z4;
    for (size_t j = i; j < N_NODES; j += stride) d_Dinv[j] = 0.f;
    for (size_t j = i; j < N_EDGES; j += stride) d_Binv[j] = 0.f;
    for (size_t j = i; j < C * C; j += stride) d_gram[j] = 0.f;
}

// ---------------- degrees (accumulate counts into d_Dinv/d_Binv) ----------------
__global__ void degree_kernel(const int* __restrict__ nidx, const int* __restrict__ eidx) {
    int i = blockIdx.x * blockDim.x + threadIdx.x;
    if (i < NNZ) {
        atomicAdd(&d_Dinv[nidx[i]], 1.f);
        atomicAdd(&d_Binv[eidx[i]], 1.f);
    }
}

// ---------------- convert counts -> reciprocals ----------------
__global__ void recip_kernel() {
    int i = blockIdx.x * blockDim.x + threadIdx.x;
    if (i < N_NODES) {
        float d = d_Dinv[i];
        d_Dinv[i] = d > 0.f ? 1.f / d : 0.f;
    }
    if (i < N_EDGES) {
        float b = d_Binv[i];
        d_Binv[i] = b > 0.f ? 1.f / b : 0.f;
    }
}

// ---------------- scatter 1: e0 += emb[node] ----------------
// 64 threads per incidence, one float4 per thread.
__global__ void scatter1_kernel(const float* __restrict__ emb,
                                const int* __restrict__ nidx,
                                const int* __restrict__ eidx) {
    long long t = (long long)blockIdx.x * blockDim.x + threadIdx.x;
    int inc = (int)(t >> 6);
    if (inc >= NNZ) return;
    int c = ((int)t & 63) << 2;
    int nr = __ldg(nidx + inc);
    int er = __ldg(eidx + inc);
    float4 v = *(const float4*)(emb + (size_t)nr * C + c);
    red_add4(d_e0 + (size_t)er * C + c, v);
}

// ---------------- edge GEMM: e1 = Binv * (e0 @ W^T) ----------------
// 128x128 tile, BK=16, 256 threads, 8x8 per thread. Only 10000 rows.
#define BM 128
#define BN 128
#define BK 16

__global__ __launch_bounds__(256)
void edge_gemm_kernel(const float* __restrict__ W) {
    __shared__ __align__(16) float As[BK][BM + 4];
    __shared__ __align__(16) float Bs[BK][BN + 4];
    int rowBase = blockIdx.x * BM;
    int colBase = blockIdx.y * BN;
    int tid = threadIdx.x;
    int tx = tid & 15, ty = tid >> 4;
    float acc[8][8] = {};

    for (int k0 = 0; k0 < C; k0 += BK) {
        #pragma unroll
        for (int l = 0; l < 2; l++) {
            int idx = tid + l * 256;
            int r  = idx >> 2;          // 0..127
            int k4 = (idx & 3) << 2;    // 0,4,8,12
            float4 v = make_float4(0.f, 0.f, 0.f, 0.f);
            int gr = rowBase + r;
            if (gr < N_EDGES) v = *(const float4*)(d_e0 + (size_t)gr * C + k0 + k4);
            As[k4 + 0][r] = v.x; As[k4 + 1][r] = v.y; As[k4 + 2][r] = v.z; As[k4 + 3][r] = v.w;
            float4 w = *(const float4*)(W + (size_t)(colBase + r) * C + k0 + k4);
            Bs[k4 + 0][r] = w.x; Bs[k4 + 1][r] = w.y; Bs[k4 + 2][r] = w.z; Bs[k4 + 3][r] = w.w;
        }
        __syncthreads();
        #pragma unroll
        for (int k = 0; k < BK; k++) {
            float4 a0 = *(const float4*)&As[k][ty * 8];
            float4 a1 = *(const float4*)&As[k][ty * 8 + 4];
            float4 b0 = *(const float4*)&Bs[k][tx * 8];
            float4 b1 = *(const float4*)&Bs[k][tx * 8 + 4];
            float a[8] = {a0.x, a0.y, a0.z, a0.w, a1.x, a1.y, a1.z, a1.w};
            float b[8] = {b0.x, b0.y, b0.z, b0.w, b1.x, b1.y, b1.z, b1.w};
            #pragma unroll
            for (int i = 0; i < 8; i++)
                #pragma unroll
                for (int j = 0; j < 8; j++)
                    acc[i][j] += a[i] * b[j];
        }
        __syncthreads();
    }

    #pragma unroll
    for (int i = 0; i < 8; i++) {
        int r = rowBase + ty * 8 + i;
        if (r < N_EDGES) {
            float binv = d_Binv[r];
            #pragma unroll
            for (int jg = 0; jg < 2; jg++) {
                int c0 = colBase + tx * 8 + jg * 4;
                float4 o;
                o.x = acc[i][jg * 4 + 0] * binv;
                o.y = acc[i][jg * 4 + 1] * binv;
                o.z = acc[i][jg * 4 + 2] * binv;
                o.w = acc[i][jg * 4 + 3] * binv;
                *(float4*)(d_e1 + (size_t)r * C + c0) = o;
            }
        }
    }
}

// ---------------- scatter 2: zw += e1[edge] ----------------
__global__ void scatter2_kernel(const int* __restrict__ nidx,
                                const int* __restrict__ eidx) {
    long long t = (long long)blockIdx.x * blockDim.x + threadIdx.x;
    int inc = (int)(t >> 6);
    if (inc >= NNZ) return;
    int c = ((int)t & 63) << 2;
    int nr = __ldg(nidx + inc);
    int er = __ldg(eidx + inc);
    float4 v = *(const float4*)(d_e1 + (size_t)er * C + c);
    red_add4(d_zw + (size_t)nr * C + c, v);
}

// ---------------- Gram: g = y^T y with fused epilogue ----------------
// y[n,c] = leaky(zw[n,c] * Dinv[n] + conv_b[c]), computed on the fly.
// Symmetric: only block pairs (0,0),(0,1),(1,1) computed; (1,0) mirrored later.
#define KC 512

__global__ __launch_bounds__(256)
void gram_kernel(const float* __restrict__ convb) {
    __shared__ __align__(16) float Ai[BK][BM + 4];
    __shared__ __align__(16) float Aj[BK][BN + 4];
    __shared__ float cb[C];
    // pair index -> (bi, bj): 0->(0,0) 1->(0,1) 2->(1,1)
    int pair = blockIdx.x;
    int bi = (pair == 2) ? 1 : 0;
    int bj = (pair == 0) ? 0 : 1;
    int ci = bi * 128;
    int cj = bj * 128;
    int k0 = blockIdx.y * KC;
    int tid = threadIdx.x;
    int tx = tid & 15, ty = tid >> 4;
    cb[tid] = convb[tid];
    float acc[8][8] = {};
    __syncthreads();

    for (int kt = k0; kt < k0 + KC; kt += BK) {
        #pragma unroll
        for (int l = 0; l < 2; l++) {
            int idx = tid + l * 256;
            int kr = idx >> 5;          // 0..15
            int c4 = (idx & 31) << 2;   // 0..124
            int gk = kt + kr;
            float4 vi = make_float4(0.f, 0.f, 0.f, 0.f);
            float4 vj = make_float4(0.f, 0.f, 0.f, 0.f);
            if (gk < N_NODES) {
                float dinv = d_Dinv[gk];
                vi = *(const float4*)(d_zw + (size_t)gk * C + ci + c4);
                vi.x = leaky(vi.x * dinv + cb[ci + c4 + 0]);
                vi.y = leaky(vi.y * dinv + cb[ci + c4 + 1]);
                vi.z = leaky(vi.z * dinv + cb[ci + c4 + 2]);
                vi.w = leaky(vi.w * dinv + cb[ci + c4 + 3]);
                vj = *(const float4*)(d_zw + (size_t)gk * C + cj + c4);
                vj.x = leaky(vj.x * dinv + cb[cj + c4 + 0]);
                vj.y = leaky(vj.y * dinv + cb[cj + c4 + 1]);
                vj.z = leaky(vj.z * dinv + cb[cj + c4 + 2]);
                vj.w = leaky(vj.w * dinv + cb[cj + c4 + 3]);
            }
            *(float4*)&Ai[kr][c4] = vi;
            *(float4*)&Aj[kr][c4] = vj;
        }
        __syncthreads();
        #pragma unroll
        for (int k = 0; k < BK; k++) {
            float4 a0 = *(const float4*)&Ai[k][ty * 8];
            float4 a1 = *(const float4*)&Ai[k][ty * 8 + 4];
            float4 b0 = *(const float4*)&Aj[k][tx * 8];
            float4 b1 = *(const float4*)&Aj[k][tx * 8 + 4];
            float a[8] = {a0.x, a0.y, a0.z, a0.w, a1.x, a1.y, a1.z, a1.w};
            float b[8] = {b0.x, b0.y, b0.z, b0.w, b1.x, b1.y, b1.z, b1.w};
            #pragma unroll
            for (int i = 0; i < 8; i++)
                #pragma unroll
                for (int j = 0; j < 8; j++)
                    acc[i][j] += a[i] * b[j];
        }
        __syncthreads();
    }

    #pragma unroll
    for (int i = 0; i < 8; i++)
        #pragma unroll
        for (int j = 0; j < 8; j++)
            atomicAdd(&d_gram[(size_t)(ci + ty * 8 + i) * C + cj + tx * 8 + j], acc[i][j]);
}

// ---------------- mirror lower-left Gram block from upper-right ----------------
__global__ void mirror_kernel() {
    int t = blockIdx.x * blockDim.x + threadIdx.x;  // 0..16383
    int i = t >> 7;          // 0..127  (row in upper block)
    int j = 128 + (t & 127); // 128..255
    d_gram[(size_t)j * C + i] = d_gram[(size_t)i * C + j];
}

// ---------------- final: out = leaky(gram @ lin_w^T + lin_b) ----------------
__global__ __launch_bounds__(256)
void final_kernel(const float* __restrict__ linw, const float* __restrict__ linb,
                  float* __restrict__ out) {
    __shared__ __align__(16) float As[16][68];
    __shared__ __align__(16) float Bs[16][68];
    int rowBase = blockIdx.y * 64;
    int colBase = blockIdx.x * 64;
    int tid = threadIdx.x;
    int tx = tid & 15, ty = tid >> 4;
    float acc[4][4] = {};

    for (int k0 = 0; k0 < C; k0 += 16) {
        int r  = tid >> 2;          // 0..63
        int k4 = (tid & 3) << 2;
        float4 v = *(const float4*)(d_gram + (size_t)(rowBase + r) * C + k0 + k4);
        As[k4 + 0][r] = v.x; As[k4 + 1][r] = v.y; As[k4 + 2][r] = v.z; As[k4 + 3][r] = v.w;
        float4 w = *(const float4*)(linw + (size_t)(colBase + r) * C + k0 + k4);
        Bs[k4 + 0][r] = w.x; Bs[k4 + 1][r] = w.y; Bs[k4 + 2][r] = w.z; Bs[k4 + 3][r] = w.w;
        __syncthreads();
        #pragma unroll
        for (int k = 0; k < 16; k++) {
            float4 a4 = *(const float4*)&As[k][ty * 4];
            float4 b4 = *(const float4*)&Bs[k][tx * 4];
            float a[4] = {a4.x, a4.y, a4.z, a4.w};
            float b[4] = {b4.x, b4.y, b4.z, b4.w};
            #pragma unroll
            for (int i = 0; i < 4; i++)
                #pragma unroll
                for (int j = 0; j < 4; j++)
                    acc[i][j] += a[i] * b[j];
        }
        __syncthreads();
    }

    #pragma unroll
    for (int i = 0; i < 4; i++) {
        int r = rowBase + ty * 4 + i;
        int c0 = colBase + tx * 4;
        float4 o;
        o.x = leaky(acc[i][0] + __ldg(&linb[c0 + 0]));
        o.y = leaky(acc[i][1] + __ldg(&linb[c0 + 1]));
        o.z = leaky(acc[i][2] + __ldg(&linb[c0 + 2]));
        o.w = leaky(acc[i][3] + __ldg(&linb[c0 + 3]));
        *(float4*)(out + (size_t)r * C + c0) = o;
    }
}

// ---------------- launch ----------------
extern "C" void kernel_launch(void* const* d_in, const int* in_sizes, int n_in,
                              void* d_out, int out_size) {
    const float* emb    = (const float*)d_in[0];
    const float* conv_w = (const float*)d_in[1];
    const float* conv_b = (const float*)d_in[2];
    const float* lin_w  = (const float*)d_in[3];
    const float* lin_b  = (const float*)d_in[4];
    const int*   eidx_all = (const int*)d_in[5];
    const int*   nidx = eidx_all;          // edge_index[0]
    const int*   eidx = eidx_all + NNZ;    // edge_index[1]
    float* out = (float*)d_out;

    zero_kernel<<<4096, 256>>>();
    degree_kernel<<<(NNZ + 255) / 256, 256>>>(nidx, eidx);
    scatter1_kernel<<<NNZ / 4, 256>>>(emb, nidx, eidx);
    recip_kernel<<<(N_NODES + 255) / 256, 256>>>();
    edge_gemm_kernel<<<dim3((N_EDGES + BM - 1) / BM, C / BN), 256>>>(conv_w);
    scatter2_kernel<<<NNZ / 4, 256>>>(nidx, eidx);
    gram_kernel<<<dim3(3, (N_NODES + KC - 1) / KC), 256>>>(conv_b);
    mirror_kernel<<<(128 * 128) / 256, 256>>>();
    final_kernel<<<dim3(C / 64, C / 64), 256>>>(lin_w, lin_b, out);
}

// round 9
// speedup vs baseline: 1.7761x; 1.3174x over previous
#include <cuda_runtime.h>

#define N_NODES 50000
#define N_EDGES 10000
#define NNZ     800000
#define C       256
#define NEG     0.01f

// ---------------- scratch (device globals) ----------------
__device__ float d_e0[N_EDGES * C];     // edge aggregation of raw emb
__device__ float d_e1[N_EDGES * C];     // Binv * (e0 @ conv_w^T)
__device__ float d_y[N_NODES * C];      // leaky(conv output), fully fused
__device__ float d_gram[C * C];         // y^T y

__device__ int d_ecnt[N_EDGES];         // edge degree (int)
__device__ int d_ncnt[N_NODES];         // node degree (int)
__device__ int d_eoff[N_EDGES + 1];     // CSR offsets (by edge)
__device__ int d_noff[N_NODES + 1];     // CSR offsets (by node)
__device__ int d_ecur[N_EDGES];         // fill cursors
__device__ int d_ncur[N_NODES];
__device__ int d_ecsr[NNZ];             // node ids grouped by edge
__device__ int d_ncsr[NNZ];             // edge ids grouped by node

__device__ __forceinline__ float leaky(float v) {
    return v > 0.f ? v : NEG * v;
}

// ---------------- zero counts + gram ----------------
__global__ void zero_kernel() {
    int i = blockIdx.x * blockDim.x + threadIdx.x;
    int stride = gridDim.x * blockDim.x;
    for (int j = i; j < N_EDGES; j += stride) d_ecnt[j] = 0;
    for (int j = i; j < N_NODES; j += stride) d_ncnt[j] = 0;
    for (int j = i; j < C * C; j += stride) d_gram[j] = 0.f;
}

// ---------------- degrees (int counts) ----------------
__global__ void degree_kernel(const int* __restrict__ nidx, const int* __restrict__ eidx) {
    int i = blockIdx.x * blockDim.x + threadIdx.x;
    if (i < NNZ) {
        atomicAdd(&d_ncnt[nidx[i]], 1);
        atomicAdd(&d_ecnt[eidx[i]], 1);
    }
}

// ---------------- single-block exclusive scan (device-side symbol access) ----------------
// NOTE: must NOT pass __device__ global addresses from host code — on GB300 the
// host-side shadow symbol is ATS-accessible and the scan silently reads host
// memory. The arrays are referenced from device code via this device function.
template <int N>
__device__ __forceinline__ void scan_impl(const int* cnt, int* off) {
    __shared__ int sums[1024];
    int tid = threadIdx.x;
    constexpr int PER = (N + 1023) / 1024;
    int base = tid * PER;
    int s = 0;
    for (int j = 0; j < PER; j++) {
        int idx = base + j;
        if (idx < N) s += cnt[idx];
    }
    sums[tid] = s;
    __syncthreads();
    // Kogge-Stone inclusive scan
    for (int d = 1; d < 1024; d <<= 1) {
        int v = (tid >= d) ? sums[tid - d] : 0;
        __syncthreads();
        sums[tid] += v;
        __syncthreads();
    }
    int run = (tid == 0) ? 0 : sums[tid - 1];
    for (int j = 0; j < PER; j++) {
        int idx = base + j;
        if (idx < N) { off[idx] = run; run += cnt[idx]; }
    }
    if (tid == 1023) off[N] = run;
}

__global__ __launch_bounds__(1024) void scan_edges_kernel() {
    scan_impl<N_EDGES>(d_ecnt, d_eoff);
}
__global__ __launch_bounds__(1024) void scan_nodes_kernel() {
    scan_impl<N_NODES>(d_ncnt, d_noff);
}

// ---------------- init fill cursors from offsets ----------------
__global__ void initcur_kernel() {
    int i = blockIdx.x * blockDim.x + threadIdx.x;
    if (i < N_EDGES) d_ecur[i] = d_eoff[i];
    if (i < N_NODES) d_ncur[i] = d_noff[i];
}

// ---------------- build both CSR lists ----------------
__global__ void build_csr_kernel(const int* __restrict__ nidx, const int* __restrict__ eidx) {
    int i = blockIdx.x * blockDim.x + threadIdx.x;
    if (i < NNZ) {
        int n = nidx[i], e = eidx[i];
        int pe = atomicAdd(&d_ecur[e], 1);
        d_ecsr[pe] = n;
        int pn = atomicAdd(&d_ncur[n], 1);
        d_ncsr[pn] = e;
    }
}

// ---------------- gather 1: e0[e] = sum over incident nodes of emb[n] ----------------
// 64 threads per edge (one float4/thread), 4 edges per 256-thread block.
__global__ __launch_bounds__(256)
void gather_edge_kernel(const float* __restrict__ emb) {
    int seg = blockIdx.x * 4 + (threadIdx.x >> 6);
    if (seg >= N_EDGES) return;
    int lane = threadIdx.x & 63;
    int c = lane << 2;
    int beg = d_eoff[seg], end = d_eoff[seg + 1];
    float4 acc = make_float4(0.f, 0.f, 0.f, 0.f);
    int j = beg;
    for (; j + 4 <= end; j += 4) {
        int n0 = __ldg(d_ecsr + j + 0);
        int n1 = __ldg(d_ecsr + j + 1);
        int n2 = __ldg(d_ecsr + j + 2);
        int n3 = __ldg(d_ecsr + j + 3);
        float4 v0 = *(const float4*)(emb + (size_t)n0 * C + c);
        float4 v1 = *(const float4*)(emb + (size_t)n1 * C + c);
        float4 v2 = *(const float4*)(emb + (size_t)n2 * C + c);
        float4 v3 = *(const float4*)(emb + (size_t)n3 * C + c);
        acc.x += v0.x + v1.x + v2.x + v3.x;
        acc.y += v0.y + v1.y + v2.y + v3.y;
        acc.z += v0.z + v1.z + v2.z + v3.z;
        acc.w += v0.w + v1.w + v2.w + v3.w;
    }
    for (; j < end; j++) {
        int n = __ldg(d_ecsr + j);
        float4 v = *(const float4*)(emb + (size_t)n * C + c);
        acc.x += v.x; acc.y += v.y; acc.z += v.z; acc.w += v.w;
    }
    *(float4*)(d_e0 + (size_t)seg * C + c) = acc;
}

// ---------------- edge GEMM: e1 = Binv * (e0 @ W^T) ----------------
#define BM 128
#define BN 128
#define BK 16

__global__ __launch_bounds__(256)
void edge_gemm_kernel(const float* __restrict__ W) {
    __shared__ __align__(16) float As[BK][BM + 4];
    __shared__ __align__(16) float Bs[BK][BN + 4];
    int rowBase = blockIdx.x * BM;
    int colBase = blockIdx.y * BN;
    int tid = threadIdx.x;
    int tx = tid & 15, ty = tid >> 4;
    float acc[8][8] = {};

    for (int k0 = 0; k0 < C; k0 += BK) {
        #pragma unroll
        for (int l = 0; l < 2; l++) {
            int idx = tid + l * 256;
            int r  = idx >> 2;
            int k4 = (idx & 3) << 2;
            float4 v = make_float4(0.f, 0.f, 0.f, 0.f);
            int gr = rowBase + r;
            if (gr < N_EDGES) v = *(const float4*)(d_e0 + (size_t)gr * C + k0 + k4);
            As[k4 + 0][r] = v.x; As[k4 + 1][r] = v.y; As[k4 + 2][r] = v.z; As[k4 + 3][r] = v.w;
            float4 w = *(const float4*)(W + (size_t)(colBase + r) * C + k0 + k4);
            Bs[k4 + 0][r] = w.x; Bs[k4 + 1][r] = w.y; Bs[k4 + 2][r] = w.z; Bs[k4 + 3][r] = w.w;
        }
        __syncthreads();
        #pragma unroll
        for (int k = 0; k < BK; k++) {
            float4 a0 = *(const float4*)&As[k][ty * 8];
            float4 a1 = *(const float4*)&As[k][ty * 8 + 4];
            float4 b0 = *(const float4*)&Bs[k][tx * 8];
            float4 b1 = *(const float4*)&Bs[k][tx * 8 + 4];
            float a[8] = {a0.x, a0.y, a0.z, a0.w, a1.x, a1.y, a1.z, a1.w};
            float b[8] = {b0.x, b0.y, b0.z, b0.w, b1.x, b1.y, b1.z, b1.w};
            #pragma unroll
            for (int i = 0; i < 8; i++)
                #pragma unroll
                for (int j = 0; j < 8; j++)
                    acc[i][j] += a[i] * b[j];
        }
        __syncthreads();
    }

    #pragma unroll
    for (int i = 0; i < 8; i++) {
        int r = rowBase + ty * 8 + i;
        if (r < N_EDGES) {
            int deg = d_eoff[r + 1] - d_eoff[r];
            float binv = deg > 0 ? 1.f / (float)deg : 0.f;
            #pragma unroll
            for (int jg = 0; jg < 2; jg++) {
                int c0 = colBase + tx * 8 + jg * 4;
                float4 o;
                o.x = acc[i][jg * 4 + 0] * binv;
                o.y = acc[i][jg * 4 + 1] * binv;
                o.z = acc[i][jg * 4 + 2] * binv;
                o.w = acc[i][jg * 4 + 3] * binv;
                *(float4*)(d_e1 + (size_t)r * C + c0) = o;
            }
        }
    }
}

// ---------------- gather 2 (fused epilogue): y[n] = leaky(Dinv*sum(e1[e]) + conv_b) ----------------
__global__ __launch_bounds__(256)
void gather_node_kernel(const float* __restrict__ convb) {
    int seg = blockIdx.x * 4 + (threadIdx.x >> 6);
    if (seg >= N_NODES) return;
    int lane = threadIdx.x & 63;
    int c = lane << 2;
    int beg = d_noff[seg], end = d_noff[seg + 1];
    float4 acc = make_float4(0.f, 0.f, 0.f, 0.f);
    int j = beg;
    for (; j + 4 <= end; j += 4) {
        int e0i = __ldg(d_ncsr + j + 0);
        int e1i = __ldg(d_ncsr + j + 1);
        int e2i = __ldg(d_ncsr + j + 2);
        int e3i = __ldg(d_ncsr + j + 3);
        float4 v0 = *(const float4*)(d_e1 + (size_t)e0i * C + c);
        float4 v1 = *(const float4*)(d_e1 + (size_t)e1i * C + c);
        float4 v2 = *(const float4*)(d_e1 + (size_t)e2i * C + c);
        float4 v3 = *(const float4*)(d_e1 + (size_t)e3i * C + c);
        acc.x += v0.x + v1.x + v2.x + v3.x;
        acc.y += v0.y + v1.y + v2.y + v3.y;
        acc.z += v0.z + v1.z + v2.z + v3.z;
        acc.w += v0.w + v1.w + v2.w + v3.w;
    }
    for (; j < end; j++) {
        int e = __ldg(d_ncsr + j);
        float4 v = *(const float4*)(d_e1 + (size_t)e * C + c);
        acc.x += v.x; acc.y += v.y; acc.z += v.z; acc.w += v.w;
    }
    int deg = end - beg;
    float dinv = deg > 0 ? 1.f / (float)deg : 0.f;
    float4 o;
    o.x = leaky(acc.x * dinv + __ldg(convb + c + 0));
    o.y = leaky(acc.y * dinv + __ldg(convb + c + 1));
    o.z = leaky(acc.z * dinv + __ldg(convb + c + 2));
    o.w = leaky(acc.w * dinv + __ldg(convb + c + 3));
    *(float4*)(d_y + (size_t)seg * C + c) = o;
}

// ---------------- Gram: g = y^T y, symmetric (3 of 4 blocks), split-K ----------------
#define KC 256

__global__ __launch_bounds__(256)
void gram_kernel() {
    __shared__ __align__(16) float Ai[BK][BM + 4];
    __shared__ __align__(16) float Aj[BK][BN + 4];
    int pair = blockIdx.x;                 // 0->(0,0) 1->(0,1) 2->(1,1)
    int ci = (pair == 2) ? 128 : 0;
    int cj = (pair == 0) ? 0 : 128;
    int k0 = blockIdx.y * KC;
    int tid = threadIdx.x;
    int tx = tid & 15, ty = tid >> 4;
    float acc[8][8] = {};

    for (int kt = k0; kt < k0 + KC; kt += BK) {
        #pragma unroll
        for (int l = 0; l < 2; l++) {
            int idx = tid + l * 256;
            int kr = idx >> 5;
            int c4 = (idx & 31) << 2;
            int gk = kt + kr;
            float4 vi = make_float4(0.f, 0.f, 0.f, 0.f);
            float4 vj = make_float4(0.f, 0.f, 0.f, 0.f);
            if (gk < N_NODES) {
                vi = *(const float4*)(d_y + (size_t)gk * C + ci + c4);
                vj = *(const float4*)(d_y + (size_t)gk * C + cj + c4);
            }
            *(float4*)&Ai[kr][c4] = vi;
            *(float4*)&Aj[kr][c4] = vj;
        }
        __syncthreads();
        #pragma unroll
        for (int k = 0; k < BK; k++) {
            float4 a0 = *(const float4*)&Ai[k][ty * 8];
            float4 a1 = *(const float4*)&Ai[k][ty * 8 + 4];
            float4 b0 = *(const float4*)&Aj[k][tx * 8];
            float4 b1 = *(const float4*)&Aj[k][tx * 8 + 4];
            float a[8] = {a0.x, a0.y, a0.z, a0.w, a1.x, a1.y, a1.z, a1.w};
            float b[8] = {b0.x, b0.y, b0.z, b0.w, b1.x, b1.y, b1.z, b1.w};
            #pragma unroll
            for (int i = 0; i < 8; i++)
                #pragma unroll
                for (int j = 0; j < 8; j++)
                    acc[i][j] += a[i] * b[j];
        }
        __syncthreads();
    }

    #pragma unroll
    for (int i = 0; i < 8; i++)
        #pragma unroll
        for (int j = 0; j < 8; j++)
            atomicAdd(&d_gram[(size_t)(ci + ty * 8 + i) * C + cj + tx * 8 + j], acc[i][j]);
}

// ---------------- mirror lower-left Gram block ----------------
__global__ void mirror_kernel() {
    int t = blockIdx.x * blockDim.x + threadIdx.x;
    int i = t >> 7;
    int j = 128 + (t & 127);
    d_gram[(size_t)j * C + i] = d_gram[(size_t)i * C + j];
}

// ---------------- final: out = leaky(gram @ lin_w^T + lin_b) ----------------
__global__ __launch_bounds__(256)
void final_kernel(const float* __restrict__ linw, const float* __restrict__ linb,
                  float* __restrict__ out) {
    __shared__ __align__(16) float As[16][68];
    __shared__ __align__(16) float Bs[16][68];
    int rowBase = blockIdx.y * 64;
    int colBase = blockIdx.x * 64;
    int tid = threadIdx.x;
    int tx = tid & 15, ty = tid >> 4;
    float acc[4][4] = {};

    for (int k0 = 0; k0 < C; k0 += 16) {
        int r  = tid >> 2;
        int k4 = (tid & 3) << 2;
        float4 v = *(const float4*)(d_gram + (size_t)(rowBase + r) * C + k0 + k4);
        As[k4 + 0][r] = v.x; As[k4 + 1][r] = v.y; As[k4 + 2][r] = v.z; As[k4 + 3][r] = v.w;
        float4 w = *(const float4*)(linw + (size_t)(colBase + r) * C + k0 + k4);
        Bs[k4 + 0][r] = w.x; Bs[k4 + 1][r] = w.y; Bs[k4 + 2][r] = w.z; Bs[k4 + 3][r] = w.w;
        __syncthreads();
        #pragma unroll
        for (int k = 0; k < 16; k++) {
            float4 a4 = *(const float4*)&As[k][ty * 4];
            float4 b4 = *(const float4*)&Bs[k][tx * 4];
            float a[4] = {a4.x, a4.y, a4.z, a4.w};
            float b[4] = {b4.x, b4.y, b4.z, b4.w};
            #pragma unroll
            for (int i = 0; i < 4; i++)
                #pragma unroll
                for (int j = 0; j < 4; j++)
                    acc[i][j] += a[i] * b[j];
        }
        __syncthreads();
    }

    #pragma unroll
    for (int i = 0; i < 4; i++) {
        int r = rowBase + ty * 4 + i;
        int c0 = colBase + tx * 4;
        float4 o;
        o.x = leaky(acc[i][0] + __ldg(&linb[c0 + 0]));
        o.y = leaky(acc[i][1] + __ldg(&linb[c0 + 1]));
        o.z = leaky(acc[i][2] + __ldg(&linb[c0 + 2]));
        o.w = leaky(acc[i][3] + __ldg(&linb[c0 + 3]));
        *(float4*)(out + (size_t)r * C + c0) = o;
    }
}

// ---------------- launch ----------------
extern "C" void kernel_launch(void* const* d_in, const int* in_sizes, int n_in,
                              void* d_out, int out_size) {
    const float* emb    = (const float*)d_in[0];
    const float* conv_w = (const float*)d_in[1];
    const float* conv_b = (const float*)d_in[2];
    const float* lin_w  = (const float*)d_in[3];
    const float* lin_b  = (const float*)d_in[4];
    const int*   eidx_all = (const int*)d_in[5];
    const int*   nidx = eidx_all;          // edge_index[0]
    const int*   eidx = eidx_all + NNZ;    // edge_index[1]
    float* out = (float*)d_out;

    zero_kernel<<<256, 256>>>();
    degree_kernel<<<(NNZ + 255) / 256, 256>>>(nidx, eidx);
    scan_edges_kernel<<<1, 1024>>>();
    scan_nodes_kernel<<<1, 1024>>>();
    initcur_kernel<<<(N_NODES + 255) / 256, 256>>>();
    build_csr_kernel<<<(NNZ + 255) / 256, 256>>>(nidx, eidx);
    gather_edge_kernel<<<(N_EDGES + 3) / 4, 256>>>(emb);
    edge_gemm_kernel<<<dim3((N_EDGES + BM - 1) / BM, C / BN), 256>>>(conv_w);
    gather_node_kernel<<<(N_NODES + 3) / 4, 256>>>(conv_b);
    gram_kernel<<<dim3(3, (N_NODES + KC - 1) / KC), 256>>>();
    mirror_kernel<<<(128 * 128) / 256, 256>>>();
    final_kernel<<<dim3(C / 64, C / 64), 256>>>(lin_w, lin_b, out);
}

// round 10
// speedup vs baseline: 1.9711x; 1.1098x over previous
#include <cuda_runtime.h>

#define N_NODES 50000
#define N_EDGES 10000
#define NNZ     800000
#define C       256
#define NEG     0.01f

#define SBLK_E  16
#define SBLK_N  64
#define CHUNK_E ((N_EDGES + SBLK_E - 1) / SBLK_E)   // 625
#define CHUNK_N ((N_NODES + SBLK_N - 1) / SBLK_N)   // 782

// ---------------- scratch (device globals) ----------------
__device__ float d_e0[N_EDGES * C];     // edge aggregation of raw emb
__device__ float d_e1[N_EDGES * C];     // Binv * (e0 @ conv_w^T)
__device__ float d_y[N_NODES * C];      // leaky(conv output), fully fused
__device__ float d_gram[C * C];         // y^T y

__device__ int d_ecnt[N_EDGES];         // edge degree (int)
__device__ int d_ncnt[N_NODES];         // node degree (int)
__device__ int d_eoff[N_EDGES + 1];     // CSR offsets (by edge)
__device__ int d_noff[N_NODES + 1];     // CSR offsets (by node)
__device__ int d_ecur[N_EDGES];         // fill cursors
__device__ int d_ncur[N_NODES];
__device__ int d_ecsr[NNZ];             // node ids grouped by edge
__device__ int d_ncsr[NNZ];             // edge ids grouped by node
__device__ int d_bsum[SBLK_E + SBLK_N]; // per-chunk sums -> exclusive bases

__device__ __forceinline__ float leaky(float v) {
    return v > 0.f ? v : NEG * v;
}

// ---------------- zero counts + gram ----------------
__global__ void zero_kernel() {
    int i = blockIdx.x * blockDim.x + threadIdx.x;
    int stride = gridDim.x * blockDim.x;
    for (int j = i; j < N_EDGES; j += stride) d_ecnt[j] = 0;
    for (int j = i; j < N_NODES; j += stride) d_ncnt[j] = 0;
    for (int j = i; j < C * C; j += stride) d_gram[j] = 0.f;
}

// ---------------- degrees (int counts) ----------------
__global__ void degree_kernel(const int* __restrict__ nidx, const int* __restrict__ eidx) {
    int i = blockIdx.x * blockDim.x + threadIdx.x;
    if (i < NNZ) {
        atomicAdd(&d_ncnt[nidx[i]], 1);
        atomicAdd(&d_ecnt[eidx[i]], 1);
    }
}

// ---------------- multi-block scan: phase A — per-chunk sums ----------------
__global__ __launch_bounds__(256)
void scan_partial_kernel() {
    __shared__ int red[256];
    int b = blockIdx.x;
    const int* cnt;
    int start, chunk;
    if (b < SBLK_E) { cnt = d_ecnt; start = b * CHUNK_E; chunk = min(CHUNK_E, N_EDGES - start); }
    else            { cnt = d_ncnt; start = (b - SBLK_E) * CHUNK_N; chunk = min(CHUNK_N, N_NODES - start); }
    int tid = threadIdx.x;
    int s = 0;
    for (int j = tid; j < chunk; j += 256) s += cnt[start + j];
    red[tid] = s;
    __syncthreads();
    for (int d = 128; d > 0; d >>= 1) {
        if (tid < d) red[tid] += red[tid + d];
        __syncthreads();
    }
    if (tid == 0) d_bsum[b] = red[0];
}

// ---------------- phase B — scan the 80 chunk sums into exclusive bases ----------------
__global__ void scan_base_kernel() {
    int tid = threadIdx.x;
    if (tid == 0) {
        int run = 0;
        for (int j = 0; j < SBLK_E; j++) { int v = d_bsum[j]; d_bsum[j] = run; run += v; }
        d_eoff[N_EDGES] = NNZ;
    }
    if (tid == 1) {
        int run = 0;
        for (int j = 0; j < SBLK_N; j++) { int v = d_bsum[SBLK_E + j]; d_bsum[SBLK_E + j] = run; run += v; }
        d_noff[N_NODES] = NNZ;
    }
}

// ---------------- phase C — write offsets + cursors (chunk <= 1024) ----------------
__global__ __launch_bounds__(1024)
void scan_write_kernel() {
    __shared__ int s[1024];
    int b = blockIdx.x;
    const int* cnt;
    int* off;
    int* cur;
    int start, chunk;
    if (b < SBLK_E) {
        cnt = d_ecnt; off = d_eoff; cur = d_ecur;
        start = b * CHUNK_E; chunk = min(CHUNK_E, N_EDGES - start);
    } else {
        cnt = d_ncnt; off = d_noff; cur = d_ncur;
        start = (b - SBLK_E) * CHUNK_N; chunk = min(CHUNK_N, N_NODES - start);
    }
    int base = d_bsum[b];
    int tid = threadIdx.x;
    int v = (tid < chunk) ? cnt[start + tid] : 0;
    s[tid] = v;
    __syncthreads();
    #pragma unroll
    for (int d = 1; d < 1024; d <<= 1) {
        int t = (tid >= d) ? s[tid - d] : 0;
        __syncthreads();
        s[tid] += t;
        __syncthreads();
    }
    if (tid < chunk) {
        int o = base + s[tid] - v;   // exclusive
        off[start + tid] = o;
        cur[start + tid] = o;
    }
}

// ---------------- build both CSR lists ----------------
__global__ void build_csr_kernel(const int* __restrict__ nidx, const int* __restrict__ eidx) {
    int i = blockIdx.x * blockDim.x + threadIdx.x;
    if (i < NNZ) {
        int n = nidx[i], e = eidx[i];
        int pe = atomicAdd(&d_ecur[e], 1);
        d_ecsr[pe] = n;
        int pn = atomicAdd(&d_ncur[n], 1);
        d_ncsr[pn] = e;
    }
}

// ---------------- gather 1: e0[e] = sum over incident nodes of emb[n] ----------------
__global__ __launch_bounds__(256)
void gather_edge_kernel(const float* __restrict__ emb) {
    int seg = blockIdx.x * 4 + (threadIdx.x >> 6);
    if (seg >= N_EDGES) return;
    int lane = threadIdx.x & 63;
    int c = lane << 2;
    int beg = d_eoff[seg], end = d_eoff[seg + 1];
    float4 acc = make_float4(0.f, 0.f, 0.f, 0.f);
    int j = beg;
    for (; j + 4 <= end; j += 4) {
        int n0 = __ldg(d_ecsr + j + 0);
        int n1 = __ldg(d_ecsr + j + 1);
        int n2 = __ldg(d_ecsr + j + 2);
        int n3 = __ldg(d_ecsr + j + 3);
        float4 v0 = *(const float4*)(emb + (size_t)n0 * C + c);
        float4 v1 = *(const float4*)(emb + (size_t)n1 * C + c);
        float4 v2 = *(const float4*)(emb + (size_t)n2 * C + c);
        float4 v3 = *(const float4*)(emb + (size_t)n3 * C + c);
        acc.x += v0.x + v1.x + v2.x + v3.x;
        acc.y += v0.y + v1.y + v2.y + v3.y;
        acc.z += v0.z + v1.z + v2.z + v3.z;
        acc.w += v0.w + v1.w + v2.w + v3.w;
    }
    for (; j < end; j++) {
        int n = __ldg(d_ecsr + j);
        float4 v = *(const float4*)(emb + (size_t)n * C + c);
        acc.x += v.x; acc.y += v.y; acc.z += v.z; acc.w += v.w;
    }
    *(float4*)(d_e0 + (size_t)seg * C + c) = acc;
}

// ---------------- edge GEMM: e1 = Binv * (e0 @ W^T) ----------------
#define BM 128
#define BN 128
#define BK 16

__global__ __launch_bounds__(256)
void edge_gemm_kernel(const float* __restrict__ W) {
    __shared__ __align__(16) float As[BK][BM + 4];
    __shared__ __align__(16) float Bs[BK][BN + 4];
    int rowBase = blockIdx.x * BM;
    int colBase = blockIdx.y * BN;
    int tid = threadIdx.x;
    int tx = tid & 15, ty = tid >> 4;
    float acc[8][8] = {};

    for (int k0 = 0; k0 < C; k0 += BK) {
        #pragma unroll
        for (int l = 0; l < 2; l++) {
            int idx = tid + l * 256;
            int r  = idx >> 2;
            int k4 = (idx & 3) << 2;
            float4 v = make_float4(0.f, 0.f, 0.f, 0.f);
            int gr = rowBase + r;
            if (gr < N_EDGES) v = *(const float4*)(d_e0 + (size_t)gr * C + k0 + k4);
            As[k4 + 0][r] = v.x; As[k4 + 1][r] = v.y; As[k4 + 2][r] = v.z; As[k4 + 3][r] = v.w;
            float4 w = *(const float4*)(W + (size_t)(colBase + r) * C + k0 + k4);
            Bs[k4 + 0][r] = w.x; Bs[k4 + 1][r] = w.y; Bs[k4 + 2][r] = w.z; Bs[k4 + 3][r] = w.w;
        }
        __syncthreads();
        #pragma unroll
        for (int k = 0; k < BK; k++) {
            float4 a0 = *(const float4*)&As[k][ty * 8];
            float4 a1 = *(const float4*)&As[k][ty * 8 + 4];
            float4 b0 = *(const float4*)&Bs[k][tx * 8];
            float4 b1 = *(const float4*)&Bs[k][tx * 8 + 4];
            float a[8] = {a0.x, a0.y, a0.z, a0.w, a1.x, a1.y, a1.z, a1.w};
            float b[8] = {b0.x, b0.y, b0.z, b0.w, b1.x, b1.y, b1.z, b1.w};
            #pragma unroll
            for (int i = 0; i < 8; i++)
                #pragma unroll
                for (int j = 0; j < 8; j++)
                    acc[i][j] += a[i] * b[j];
        }
        __syncthreads();
    }

    #pragma unroll
    for (int i = 0; i < 8; i++) {
        int r = rowBase + ty * 8 + i;
        if (r < N_EDGES) {
            int deg = d_eoff[r + 1] - d_eoff[r];
            float binv = deg > 0 ? 1.f / (float)deg : 0.f;
            #pragma unroll
            for (int jg = 0; jg < 2; jg++) {
                int c0 = colBase + tx * 8 + jg * 4;
                float4 o;
                o.x = acc[i][jg * 4 + 0] * binv;
                o.y = acc[i][jg * 4 + 1] * binv;
                o.z = acc[i][jg * 4 + 2] * binv;
                o.w = acc[i][jg * 4 + 3] * binv;
                *(float4*)(d_e1 + (size_t)r * C + c0) = o;
            }
        }
    }
}

// ---------------- gather 2 (fused epilogue): y[n] = leaky(Dinv*sum(e1[e]) + conv_b) ----------------
__global__ __launch_bounds__(256)
void gather_node_kernel(const float* __restrict__ convb) {
    int seg = blockIdx.x * 4 + (threadIdx.x >> 6);
    if (seg >= N_NODES) return;
    int lane = threadIdx.x & 63;
    int c = lane << 2;
    int beg = d_noff[seg], end = d_noff[seg + 1];
    float4 acc = make_float4(0.f, 0.f, 0.f, 0.f);
    int j = beg;
    for (; j + 4 <= end; j += 4) {
        int e0i = __ldg(d_ncsr + j + 0);
        int e1i = __ldg(d_ncsr + j + 1);
        int e2i = __ldg(d_ncsr + j + 2);
        int e3i = __ldg(d_ncsr + j + 3);
        float4 v0 = *(const float4*)(d_e1 + (size_t)e0i * C + c);
        float4 v1 = *(const float4*)(d_e1 + (size_t)e1i * C + c);
        float4 v2 = *(const float4*)(d_e1 + (size_t)e2i * C + c);
        float4 v3 = *(const float4*)(d_e1 + (size_t)e3i * C + c);
        acc.x += v0.x + v1.x + v2.x + v3.x;
        acc.y += v0.y + v1.y + v2.y + v3.y;
        acc.z += v0.z + v1.z + v2.z + v3.z;
        acc.w += v0.w + v1.w + v2.w + v3.w;
    }
    for (; j < end; j++) {
        int e = __ldg(d_ncsr + j);
        float4 v = *(const float4*)(d_e1 + (size_t)e * C + c);
        acc.x += v.x; acc.y += v.y; acc.z += v.z; acc.w += v.w;
    }
    int deg = end - beg;
    float dinv = deg > 0 ? 1.f / (float)deg : 0.f;
    float4 o;
    o.x = leaky(acc.x * dinv + __ldg(convb + c + 0));
    o.y = leaky(acc.y * dinv + __ldg(convb + c + 1));
    o.z = leaky(acc.z * dinv + __ldg(convb + c + 2));
    o.w = leaky(acc.w * dinv + __ldg(convb + c + 3));
    *(float4*)(d_y + (size_t)seg * C + c) = o;
}

// ---------------- Gram: g = y^T y, symmetric (3 of 4 blocks), split-K ----------------
// KC=1024 -> grid (3, 49) = 147 blocks ~= one full wave on 148 SMs; 4x fewer atomics.
#define KC 1024

__global__ __launch_bounds__(256)
void gram_kernel() {
    __shared__ __align__(16) float Ai[BK][BM + 4];
    __shared__ __align__(16) float Aj[BK][BN + 4];
    int pair = blockIdx.x;                 // 0->(0,0) 1->(0,1) 2->(1,1)
    int ci = (pair == 2) ? 128 : 0;
    int cj = (pair == 0) ? 0 : 128;
    int k0 = blockIdx.y * KC;
    int tid = threadIdx.x;
    int tx = tid & 15, ty = tid >> 4;
    float acc[8][8] = {};

    for (int kt = k0; kt < k0 + KC; kt += BK) {
        #pragma unroll
        for (int l = 0; l < 2; l++) {
            int idx = tid + l * 256;
            int kr = idx >> 5;
            int c4 = (idx & 31) << 2;
            int gk = kt + kr;
            float4 vi = make_float4(0.f, 0.f, 0.f, 0.f);
            float4 vj = make_float4(0.f, 0.f, 0.f, 0.f);
            if (gk < N_NODES) {
                vi = *(const float4*)(d_y + (size_t)gk * C + ci + c4);
                vj = *(const float4*)(d_y + (size_t)gk * C + cj + c4);
            }
            *(float4*)&Ai[kr][c4] = vi;
            *(float4*)&Aj[kr][c4] = vj;
        }
        __syncthreads();
        #pragma unroll
        for (int k = 0; k < BK; k++) {
            float4 a0 = *(const float4*)&Ai[k][ty * 8];
            float4 a1 = *(const float4*)&Ai[k][ty * 8 + 4];
            float4 b0 = *(const float4*)&Aj[k][tx * 8];
            float4 b1 = *(const float4*)&Aj[k][tx * 8 + 4];
            float a[8] = {a0.x, a0.y, a0.z, a0.w, a1.x, a1.y, a1.z, a1.w};
            float b[8] = {b0.x, b0.y, b0.z, b0.w, b1.x, b1.y, b1.z, b1.w};
            #pragma unroll
            for (int i = 0; i < 8; i++)
                #pragma unroll
                for (int j = 0; j < 8; j++)
                    acc[i][j] += a[i] * b[j];
        }
        __syncthreads();
    }

    #pragma unroll
    for (int i = 0; i < 8; i++)
        #pragma unroll
        for (int j = 0; j < 8; j++)
            atomicAdd(&d_gram[(size_t)(ci + ty * 8 + i) * C + cj + tx * 8 + j], acc[i][j]);
}

// ---------------- mirror lower-left Gram block ----------------
__global__ void mirror_kernel() {
    int t = blockIdx.x * blockDim.x + threadIdx.x;
    int i = t >> 7;
    int j = 128 + (t & 127);
    d_gram[(size_t)j * C + i] = d_gram[(size_t)i * C + j];
}

// ---------------- final: out = leaky(gram @ lin_w^T + lin_b) ----------------
__global__ __launch_bounds__(256)
void final_kernel(const float* __restrict__ linw, const float* __restrict__ linb,
                  float* __restrict__ out) {
    __shared__ __align__(16) float As[16][68];
    __shared__ __align__(16) float Bs[16][68];
    int rowBase = blockIdx.y * 64;
    int colBase = blockIdx.x * 64;
    int tid = threadIdx.x;
    int tx = tid & 15, ty = tid >> 4;
    float acc[4][4] = {};

    for (int k0 = 0; k0 < C; k0 += 16) {
        int r  = tid >> 2;
        int k4 = (tid & 3) << 2;
        float4 v = *(const float4*)(d_gram + (size_t)(rowBase + r) * C + k0 + k4);
        As[k4 + 0][r] = v.x; As[k4 + 1][r] = v.y; As[k4 + 2][r] = v.z; As[k4 + 3][r] = v.w;
        float4 w = *(const float4*)(linw + (size_t)(colBase + r) * C + k0 + k4);
        Bs[k4 + 0][r] = w.x; Bs[k4 + 1][r] = w.y; Bs[k4 + 2][r] = w.z; Bs[k4 + 3][r] = w.w;
        __syncthreads();
        #pragma unroll
        for (int k = 0; k < 16; k++) {
            float4 a4 = *(const float4*)&As[k][ty * 4];
            float4 b4 = *(const float4*)&Bs[k][tx * 4];
            float a[4] = {a4.x, a4.y, a4.z, a4.w};
            float b[4] = {b4.x, b4.y, b4.z, b4.w};
            #pragma unroll
            for (int i = 0; i < 4; i++)
                #pragma unroll
                for (int j = 0; j < 4; j++)
                    acc[i][j] += a[i] * b[j];
        }
        __syncthreads();
    }

    #pragma unroll
    for (int i = 0; i < 4; i++) {
        int r = rowBase + ty * 4 + i;
        int c0 = colBase + tx * 4;
        float4 o;
        o.x = leaky(acc[i][0] + __ldg(&linb[c0 + 0]));
        o.y = leaky(acc[i][1] + __ldg(&linb[c0 + 1]));
        o.z = leaky(acc[i][2] + __ldg(&linb[c0 + 2]));
        o.w = leaky(acc[i][3] + __ldg(&linb[c0 + 3]));
        *(float4*)(out + (size_t)r * C + c0) = o;
    }
}

// ---------------- launch ----------------
extern "C" void kernel_launch(void* const* d_in, const int* in_sizes, int n_in,
                              void* d_out, int out_size) {
    const float* emb    = (const float*)d_in[0];
    const float* conv_w = (const float*)d_in[1];
    const float* conv_b = (const float*)d_in[2];
    const float* lin_w  = (const float*)d_in[3];
    const float* lin_b  = (const float*)d_in[4];
    const int*   eidx_all = (const int*)d_in[5];
    const int*   nidx = eidx_all;          // edge_index[0]
    const int*   eidx = eidx_all + NNZ;    // edge_index[1]
    float* out = (float*)d_out;

    zero_kernel<<<256, 256>>>();
    degree_kernel<<<(NNZ + 255) / 256, 256>>>(nidx, eidx);
    scan_partial_kernel<<<SBLK_E + SBLK_N, 256>>>();
    scan_base_kernel<<<1, 32>>>();
    scan_write_kernel<<<SBLK_E + SBLK_N, 1024>>>();
    build_csr_kernel<<<(NNZ + 255) / 256, 256>>>(nidx, eidx);
    gather_edge_kernel<<<(N_EDGES + 3) / 4, 256>>>(emb);
    edge_gemm_kernel<<<dim3((N_EDGES + BM - 1) / BM, C / BN), 256>>>(conv_w);
    gather_node_kernel<<<(N_NODES + 3) / 4, 256>>>(conv_b);
    gram_kernel<<<dim3(3, (N_NODES + KC - 1) / KC), 256>>>();
    mirror_kernel<<<(128 * 128) / 256, 256>>>();
    final_kernel<<<dim3(C / 64, C / 64), 256>>>(lin_w, lin_b, out);
}

// round 14
// speedup vs baseline: 2.0076x; 1.0185x over previous
#include <cuda_runtime.h>
#include <cstdint>

#define N_NODES 50000
#define N_EDGES 10000
#define NNZ     800000
#define C       256
#define NEG     0.01f

#define SBLK_E  16
#define SBLK_N  64
#define CHUNK_E ((N_EDGES + SBLK_E - 1) / SBLK_E)   // 625
#define CHUNK_N ((N_NODES + SBLK_N - 1) / SBLK_N)   // 782

// ---------------- scratch (device globals) ----------------
__device__ float d_e0[N_EDGES * C];     // edge aggregation of raw emb
__device__ float d_e1[N_EDGES * C];     // Binv * (e0 @ conv_w^T)
__device__ float d_y[N_NODES * C];      // leaky(conv output), fully fused
__device__ float d_gram[C * C];         // y^T y

__device__ int d_ecnt[N_EDGES];         // edge degree (int)
__device__ int d_ncnt[N_NODES];         // node degree (int)
__device__ int d_eoff[N_EDGES + 1];     // CSR offsets (by edge)
__device__ int d_noff[N_NODES + 1];     // CSR offsets (by node)
__device__ int d_ecur[N_EDGES];         // fill cursors
__device__ int d_ncur[N_NODES];
__device__ int d_ecsr[NNZ];             // node ids grouped by edge
__device__ int d_ncsr[NNZ];             // edge ids grouped by node
__device__ int d_bsum[SBLK_E + SBLK_N]; // per-chunk sums -> exclusive bases

__device__ __forceinline__ float leaky(float v) {
    return v > 0.f ? v : NEG * v;
}

__device__ __forceinline__ uint32_t to_tf32(float v) {
    uint32_t r;
    asm("cvt.rna.tf32.f32 %0, %1;" : "=r"(r) : "f"(v));
    return r;
}

__device__ __forceinline__ void mma_tf32(float* c, const uint32_t* a, const uint32_t* b) {
    asm volatile(
        "mma.sync.aligned.m16n8k8.row.col.f32.tf32.tf32.f32 "
        "{%0,%1,%2,%3}, {%4,%5,%6,%7}, {%8,%9}, {%0,%1,%2,%3};"
        : "+f"(c[0]), "+f"(c[1]), "+f"(c[2]), "+f"(c[3])
        : "r"(a[0]), "r"(a[1]), "r"(a[2]), "r"(a[3]), "r"(b[0]), "r"(b[1]));
}

// ---------------- zero counts + gram ----------------
__global__ void zero_kernel() {
    int i = blockIdx.x * blockDim.x + threadIdx.x;
    int stride = gridDim.x * blockDim.x;
    for (int j = i; j < N_EDGES; j += stride) d_ecnt[j] = 0;
    for (int j = i; j < N_NODES; j += stride) d_ncnt[j] = 0;
    for (int j = i; j < C * C; j += stride) d_gram[j] = 0.f;
}

// ---------------- degrees (int counts) ----------------
__global__ void degree_kernel(const int* __restrict__ nidx, const int* __restrict__ eidx) {
    int i = blockIdx.x * blockDim.x + threadIdx.x;
    if (i < NNZ) {
        atomicAdd(&d_ncnt[nidx[i]], 1);
        atomicAdd(&d_ecnt[eidx[i]], 1);
    }
}

// ---------------- multi-block scan: phase A — per-chunk sums ----------------
__global__ __launch_bounds__(256)
void scan_partial_kernel() {
    __shared__ int red[256];
    int b = blockIdx.x;
    const int* cnt;
    int start, chunk;
    if (b < SBLK_E) { cnt = d_ecnt; start = b * CHUNK_E; chunk = min(CHUNK_E, N_EDGES - start); }
    else            { cnt = d_ncnt; start = (b - SBLK_E) * CHUNK_N; chunk = min(CHUNK_N, N_NODES - start); }
    int tid = threadIdx.x;
    int s = 0;
    for (int j = tid; j < chunk; j += 256) s += cnt[start + j];
    red[tid] = s;
    __syncthreads();
    for (int d = 128; d > 0; d >>= 1) {
        if (tid < d) red[tid] += red[tid + d];
        __syncthreads();
    }
    if (tid == 0) d_bsum[b] = red[0];
}

// ---------------- phase B — scan the 80 chunk sums into exclusive bases ----------------
__global__ void scan_base_kernel() {
    int tid = threadIdx.x;
    if (tid == 0) {
        int run = 0;
        for (int j = 0; j < SBLK_E; j++) { int v = d_bsum[j]; d_bsum[j] = run; run += v; }
        d_eoff[N_EDGES] = NNZ;
    }
    if (tid == 1) {
        int run = 0;
        for (int j = 0; j < SBLK_N; j++) { int v = d_bsum[SBLK_E + j]; d_bsum[SBLK_E + j] = run; run += v; }
        d_noff[N_NODES] = NNZ;
    }
}

// ---------------- phase C — write offsets + cursors (chunk <= 1024) ----------------
__global__ __launch_bounds__(1024)
void scan_write_kernel() {
    __shared__ int s[1024];
    int b = blockIdx.x;
    const int* cnt;
    int* off;
    int* cur;
    int start, chunk;
    if (b < SBLK_E) {
        cnt = d_ecnt; off = d_eoff; cur = d_ecur;
        start = b * CHUNK_E; chunk = min(CHUNK_E, N_EDGES - start);
    } else {
        cnt = d_ncnt; off = d_noff; cur = d_ncur;
        start = (b - SBLK_E) * CHUNK_N; chunk = min(CHUNK_N, N_NODES - start);
    }
    int base = d_bsum[b];
    int tid = threadIdx.x;
    int v = (tid < chunk) ? cnt[start + tid] : 0;
    s[tid] = v;
    __syncthreads();
    #pragma unroll
    for (int d = 1; d < 1024; d <<= 1) {
        int t = (tid >= d) ? s[tid - d] : 0;
        __syncthreads();
        s[tid] += t;
        __syncthreads();
    }
    if (tid < chunk) {
        int o = base + s[tid] - v;   // exclusive
        off[start + tid] = o;
        cur[start + tid] = o;
    }
}

// ---------------- build both CSR lists ----------------
__global__ void build_csr_kernel(const int* __restrict__ nidx, const int* __restrict__ eidx) {
    int i = blockIdx.x * blockDim.x + threadIdx.x;
    if (i < NNZ) {
        int n = nidx[i], e = eidx[i];
        int pe = atomicAdd(&d_ecur[e], 1);
        d_ecsr[pe] = n;
        int pn = atomicAdd(&d_ncur[n], 1);
        d_ncsr[pn] = e;
    }
}

// ---------------- gather 1: e0[e] = sum over incident nodes of emb[n] ----------------
__global__ __launch_bounds__(256)
void gather_edge_kernel(const float* __restrict__ emb) {
    int seg = blockIdx.x * 4 + (threadIdx.x >> 6);
    if (seg >= N_EDGES) return;
    int lane = threadIdx.x & 63;
    int c = lane << 2;
    int beg = d_eoff[seg], end = d_eoff[seg + 1];
    float4 acc = make_float4(0.f, 0.f, 0.f, 0.f);
    int j = beg;
    for (; j + 4 <= end; j += 4) {
        int n0 = __ldg(d_ecsr + j + 0);
        int n1 = __ldg(d_ecsr + j + 1);
        int n2 = __ldg(d_ecsr + j + 2);
        int n3 = __ldg(d_ecsr + j + 3);
        float4 v0 = *(const float4*)(emb + (size_t)n0 * C + c);
        float4 v1 = *(const float4*)(emb + (size_t)n1 * C + c);
        float4 v2 = *(const float4*)(emb + (size_t)n2 * C + c);
        float4 v3 = *(const float4*)(emb + (size_t)n3 * C + c);
        acc.x += v0.x + v1.x + v2.x + v3.x;
        acc.y += v0.y + v1.y + v2.y + v3.y;
        acc.z += v0.z + v1.z + v2.z + v3.z;
        acc.w += v0.w + v1.w + v2.w + v3.w;
    }
    for (; j < end; j++) {
        int n = __ldg(d_ecsr + j);
        float4 v = *(const float4*)(emb + (size_t)n * C + c);
        acc.x += v.x; acc.y += v.y; acc.z += v.z; acc.w += v.w;
    }
    *(float4*)(d_e0 + (size_t)seg * C + c) = acc;
}

// ---------------- edge GEMM: e1 = Binv * (e0 @ W^T), fp32 FFMA ----------------
// (stays fp32: sums over random-sign W would turn tf32 rounding into ~2e-4 output error)
#define BM 128
#define BN 128
#define BK 16

__global__ __launch_bounds__(256)
void edge_gemm_kernel(const float* __restrict__ W) {
    __shared__ __align__(16) float As[BK][BM + 4];
    __shared__ __align__(16) float Bs[BK][BN + 4];
    int rowBase = blockIdx.x * BM;
    int colBase = blockIdx.y * BN;
    int tid = threadIdx.x;
    int tx = tid & 15, ty = tid >> 4;
    float acc[8][8] = {};

    for (int k0 = 0; k0 < C; k0 += BK) {
        #pragma unroll
        for (int l = 0; l < 2; l++) {
            int idx = tid + l * 256;
            int r  = idx >> 2;
            int k4 = (idx & 3) << 2;
            float4 v = make_float4(0.f, 0.f, 0.f, 0.f);
            int gr = rowBase + r;
            if (gr < N_EDGES) v = *(const float4*)(d_e0 + (size_t)gr * C + k0 + k4);
            As[k4 + 0][r] = v.x; As[k4 + 1][r] = v.y; As[k4 + 2][r] = v.z; As[k4 + 3][r] = v.w;
            float4 w = *(const float4*)(W + (size_t)(colBase + r) * C + k0 + k4);
            Bs[k4 + 0][r] = w.x; Bs[k4 + 1][r] = w.y; Bs[k4 + 2][r] = w.z; Bs[k4 + 3][r] = w.w;
        }
        __syncthreads();
        #pragma unroll
        for (int k = 0; k < BK; k++) {
            float4 a0 = *(const float4*)&As[k][ty * 8];
            float4 a1 = *(const float4*)&As[k][ty * 8 + 4];
            float4 b0 = *(const float4*)&Bs[k][tx * 8];
            float4 b1 = *(const float4*)&Bs[k][tx * 8 + 4];
            float a[8] = {a0.x, a0.y, a0.z, a0.w, a1.x, a1.y, a1.z, a1.w};
            float b[8] = {b0.x, b0.y, b0.z, b0.w, b1.x, b1.y, b1.z, b1.w};
            #pragma unroll
            for (int i = 0; i < 8; i++)
                #pragma unroll
                for (int j = 0; j < 8; j++)
                    acc[i][j] += a[i] * b[j];
        }
        __syncthreads();
    }

    #pragma unroll
    for (int i = 0; i < 8; i++) {
        int r = rowBase + ty * 8 + i;
        if (r < N_EDGES) {
            int deg = d_eoff[r + 1] - d_eoff[r];
            float binv = deg > 0 ? 1.f / (float)deg : 0.f;
            #pragma unroll
            for (int jg = 0; jg < 2; jg++) {
                int c0 = colBase + tx * 8 + jg * 4;
                float4 o;
                o.x = acc[i][jg * 4 + 0] * binv;
                o.y = acc[i][jg * 4 + 1] * binv;
                o.z = acc[i][jg * 4 + 2] * binv;
                o.w = acc[i][jg * 4 + 3] * binv;
                *(float4*)(d_e1 + (size_t)r * C + c0) = o;
            }
        }
    }
}

// ---------------- gather 2 (fused epilogue): y[n] = leaky(Dinv*sum(e1[e]) + conv_b) ----------------
__global__ __launch_bounds__(256)
void gather_node_kernel(const float* __restrict__ convb) {
    int seg = blockIdx.x * 4 + (threadIdx.x >> 6);
    if (seg >= N_NODES) return;
    int lane = threadIdx.x & 63;
    int c = lane << 2;
    int beg = d_noff[seg], end = d_noff[seg + 1];
    float4 acc = make_float4(0.f, 0.f, 0.f, 0.f);
    int j = beg;
    for (; j + 4 <= end; j += 4) {
        int e0i = __ldg(d_ncsr + j + 0);
        int e1i = __ldg(d_ncsr + j + 1);
        int e2i = __ldg(d_ncsr + j + 2);
        int e3i = __ldg(d_ncsr + j + 3);
        float4 v0 = *(const float4*)(d_e1 + (size_t)e0i * C + c);
        float4 v1 = *(const float4*)(d_e1 + (size_t)e1i * C + c);
        float4 v2 = *(const float4*)(d_e1 + (size_t)e2i * C + c);
        float4 v3 = *(const float4*)(d_e1 + (size_t)e3i * C + c);
        acc.x += v0.x + v1.x + v2.x + v3.x;
        acc.y += v0.y + v1.y + v2.y + v3.y;
        acc.z += v0.z + v1.z + v2.z + v3.z;
        acc.w += v0.w + v1.w + v2.w + v3.w;
    }
    for (; j < end; j++) {
        int e = __ldg(d_ncsr + j);
        float4 v = *(const float4*)(d_e1 + (size_t)e * C + c);
        acc.x += v.x; acc.y += v.y; acc.z += v.z; acc.w += v.w;
    }
    int deg = end - beg;
    float dinv = deg > 0 ? 1.f / (float)deg : 0.f;
    float4 o;
    o.x = leaky(acc.x * dinv + __ldg(convb + c + 0));
    o.y = leaky(acc.y * dinv + __ldg(convb + c + 1));
    o.z = leaky(acc.z * dinv + __ldg(convb + c + 2));
    o.w = leaky(acc.w * dinv + __ldg(convb + c + 3));
    *(float4*)(d_y + (size_t)seg * C + c) = o;
}

// ---------------- Gram: g = y^T y via tf32 mma.sync, symmetric 3-block, split-K ----
// Block: 128x128 output tile; 8 warps as 2x4 -> 64x32 per warp (4x4 m16n8k8 tiles).
// Smem slab: BKK=32 k-rows stored [k][c] with pitch 136 floats (conflict-free frags).
#define KC   1024
#define BKK  32
#define GP   136   // smem pitch in floats

__global__ __launch_bounds__(256)
void gram_kernel() {
    __shared__ uint32_t Yi[BKK * GP];
    __shared__ uint32_t Yj[BKK * GP];
    int pair = blockIdx.x;                 // 0->(0,0) 1->(0,1) 2->(1,1)
    int ci = (pair == 2) ? 128 : 0;
    int cj = (pair == 0) ? 0 : 128;
    int k0 = blockIdx.y * KC;
    int tid = threadIdx.x;
    int lane = tid & 31;
    int warp = tid >> 5;
    int MB = (warp >> 2) * 64;             // warp row base within 128
    int NB = (warp & 3) * 32;              // warp col base within 128

    float acc[4][4][4] = {};

    for (int kt = k0; kt < k0 + KC; kt += BKK) {
        // load + convert BKK x 128 slabs of both column ranges
        #pragma unroll
        for (int it = 0; it < 4; it++) {
            int idx = it * 256 + tid;      // 0..1023
            int k  = idx >> 5;             // 0..31
            int c4 = (idx & 31) << 2;      // 0..124
            int gk = kt + k;
            float4 vi = make_float4(0.f, 0.f, 0.f, 0.f);
            float4 vj = make_float4(0.f, 0.f, 0.f, 0.f);
            if (gk < N_NODES) {
                vi = *(const float4*)(d_y + (size_t)gk * C + ci + c4);
                vj = *(const float4*)(d_y + (size_t)gk * C + cj + c4);
            }
            uint4 ti, tj;
            ti.x = to_tf32(vi.x); ti.y = to_tf32(vi.y); ti.z = to_tf32(vi.z); ti.w = to_tf32(vi.w);
            tj.x = to_tf32(vj.x); tj.y = to_tf32(vj.y); tj.z = to_tf32(vj.z); tj.w = to_tf32(vj.w);
            *(uint4*)&Yi[k * GP + c4] = ti;
            *(uint4*)&Yj[k * GP + c4] = tj;
        }
        __syncthreads();

        #pragma unroll
        for (int ks = 0; ks < 4; ks++) {
            int kb = ks * 8 + (lane & 3);
            int mrow = MB + (lane >> 2);
            int ncol = NB + (lane >> 2);
            uint32_t a[4][4];
            #pragma unroll
            for (int mt = 0; mt < 4; mt++) {
                a[mt][0] = Yi[kb * GP + mrow + mt * 16];
                a[mt][1] = Yi[kb * GP + mrow + mt * 16 + 8];
                a[mt][2] = Yi[(kb + 4) * GP + mrow + mt * 16];
                a[mt][3] = Yi[(kb + 4) * GP + mrow + mt * 16 + 8];
            }
            uint32_t b[4][2];
            #pragma unroll
            for (int nt = 0; nt < 4; nt++) {
                b[nt][0] = Yj[kb * GP + ncol + nt * 8];
                b[nt][1] = Yj[(kb + 4) * GP + ncol + nt * 8];
            }
            #pragma unroll
            for (int mt = 0; mt < 4; mt++)
                #pragma unroll
                for (int nt = 0; nt < 4; nt++)
                    mma_tf32(acc[mt][nt], a[mt], b[nt]);
        }
        __syncthreads();
    }

    // epilogue: atomic accumulate into d_gram
    #pragma unroll
    for (int mt = 0; mt < 4; mt++) {
        #pragma unroll
        for (int nt = 0; nt < 4; nt++) {
            int r0 = ci + MB + mt * 16 + (lane >> 2);
            int c0 = cj + NB + nt * 8 + 2 * (lane & 3);
            atomicAdd(&d_gram[(size_t)r0 * C + c0],           acc[mt][nt][0]);
            atomicAdd(&d_gram[(size_t)r0 * C + c0 + 1],       acc[mt][nt][1]);
            atomicAdd(&d_gram[(size_t)(r0 + 8) * C + c0],     acc[mt][nt][2]);
            atomicAdd(&d_gram[(size_t)(r0 + 8) * C + c0 + 1], acc[mt][nt][3]);
        }
    }
}

// ---------------- mirror lower-left Gram block ----------------
__global__ void mirror_kernel() {
    int t = blockIdx.x * blockDim.x + threadIdx.x;
    int i = t >> 7;
    int j = 128 + (t & 127);
    d_gram[(size_t)j * C + i] = d_gram[(size_t)i * C + j];
}

// ---------------- final: out = leaky(gram @ lin_w^T + lin_b) ----------------
__global__ __launch_bounds__(256)
void final_kernel(const float* __restrict__ linw, const float* __restrict__ linb,
                  float* __restrict__ out) {
    __shared__ __align__(16) float As[16][68];
    __shared__ __align__(16) float Bs[16][68];
    int rowBase = blockIdx.y * 64;
    int colBase = blockIdx.x * 64;
    int tid = threadIdx.x;
    int tx = tid & 15, ty = tid >> 4;
    float acc[4][4] = {};

    for (int k0 = 0; k0 < C; k0 += 16) {
        int r  = tid >> 2;
        int k4 = (tid & 3) << 2;
        float4 v = *(const float4*)(d_gram + (size_t)(rowBase + r) * C + k0 + k4);
        As[k4 + 0][r] = v.x; As[k4 + 1][r] = v.y; As[k4 + 2][r] = v.z; As[k4 + 3][r] = v.w;
        float4 w = *(const float4*)(linw + (size_t)(colBase + r) * C + k0 + k4);
        Bs[k4 + 0][r] = w.x; Bs[k4 + 1][r] = w.y; Bs[k4 + 2][r] = w.z; Bs[k4 + 3][r] = w.w;
        __syncthreads();
        #pragma unroll
        for (int k = 0; k < 16; k++) {
            float4 a4 = *(const float4*)&As[k][ty * 4];
            float4 b4 = *(const float4*)&Bs[k][tx * 4];
            float a[4] = {a4.x, a4.y, a4.z, a4.w};
            float b[4] = {b4.x, b4.y, b4.z, b4.w};
            #pragma unroll
            for (int i = 0; i < 4; i++)
                #pragma unroll
                for (int j = 0; j < 4; j++)
                    acc[i][j] += a[i] * b[j];
        }
        __syncthreads();
    }

    #pragma unroll
    for (int i = 0; i < 4; i++) {
        int r = rowBase + ty * 4 + i;
        int c0 = colBase + tx * 4;
        float4 o;
        o.x = leaky(acc[i][0] + __ldg(&linb[c0 + 0]));
        o.y = leaky(acc[i][1] + __ldg(&linb[c0 + 1]));
        o.z = leaky(acc[i][2] + __ldg(&linb[c0 + 2]));
        o.w = leaky(acc[i][3] + __ldg(&linb[c0 + 3]));
        *(float4*)(out + (size_t)r * C + c0) = o;
    }
}

// ---------------- launch ----------------
extern "C" void kernel_launch(void* const* d_in, const int* in_sizes, int n_in,
                              void* d_out, int out_size) {
    const float* emb    = (const float*)d_in[0];
    const float* conv_w = (const float*)d_in[1];
    const float* conv_b = (const float*)d_in[2];
    const float* lin_w  = (const float*)d_in[3];
    const float* lin_b  = (const float*)d_in[4];
    const int*   eidx_all = (const int*)d_in[5];
    const int*   nidx = eidx_all;          // edge_index[0]
    const int*   eidx = eidx_all + NNZ;    // edge_index[1]
    float* out = (float*)d_out;

    zero_kernel<<<256, 256>>>();
    degree_kernel<<<(NNZ + 255) / 256, 256>>>(nidx, eidx);
    scan_partial_kernel<<<SBLK_E + SBLK_N, 256>>>();
    scan_base_kernel<<<1, 32>>>();
    scan_write_kernel<<<SBLK_E + SBLK_N, 1024>>>();
    build_csr_kernel<<<(NNZ + 255) / 256, 256>>>(nidx, eidx);
    gather_edge_kernel<<<(N_EDGES + 3) / 4, 256>>>(emb);
    edge_gemm_kernel<<<dim3((N_EDGES + BM - 1) / BM, C / BN), 256>>>(conv_w);
    gather_node_kernel<<<(N_NODES + 3) / 4, 256>>>(conv_b);
    gram_kernel<<<dim3(3, (N_NODES + KC - 1) / KC), 256>>>();
    mirror_kernel<<<(128 * 128) / 256, 256>>>();
    final_kernel<<<dim3(C / 64, C / 64), 256>>>(lin_w, lin_b, out);
}